// round 9
// baseline (speedup 1.0000x reference)
#include <cuda_runtime.h>
#include <cstdint>

// ============================================================================
// Binary CNN (XNOR-net style), fully fused. R5 passing baseline = 675.9us.
// R6 changes (no arithmetic changes -> numerics identical to R5):
//   - ws smem layout [tap][vec][lane] (uint4 lane-major) -> conflict-free LDS.128
//   - non-pool layers keep all 9 taps' weights in registers (no w LDS in loop)
//   - 5 pack kernels fused into 1 launch
//   - conv1 processes 2 pixels per iteration (2 independent FMA chains;
//     per-output FMA order unchanged)
// ============================================================================

#define DEVFN __device__ __forceinline__

// ---------------- scratch (device globals; no allocation) -------------------
__device__ unsigned int g_xb1[128 * 32 * 32 * 4];   // after conv1 block (sign bits)
__device__ unsigned int g_xb2[128 * 16 * 16 * 4];   // after conv2 block
__device__ unsigned int g_xb3[128 * 16 * 16 * 8];   // after conv3 block
__device__ unsigned int g_xb4[128 * 8 * 8 * 8];     // after conv4 block
__device__ unsigned int g_xb5[128 * 8 * 8 * 16];    // after conv5 block
__device__ float        g_h6[128 * 4 * 4 * 512];    // after conv6 block (float)

__device__ unsigned int g_wb2[9 * 128 * 4];   // packed weights [tap][co][ciw]
__device__ unsigned int g_wb3[9 * 256 * 4];
__device__ unsigned int g_wb4[9 * 256 * 8];
__device__ unsigned int g_wb5[9 * 512 * 8];
__device__ unsigned int g_wb6[9 * 512 * 16];

// ---------------- per-layer config ------------------------------------------
template <int L> struct Cfg;
template <> struct Cfg<2> { static constexpr int H = 32, W = 32, CI = 128, CO = 128; static constexpr bool POOL = true,  OUTF = false; };
template <> struct Cfg<3> { static constexpr int H = 16, W = 16, CI = 128, CO = 256; static constexpr bool POOL = false, OUTF = false; };
template <> struct Cfg<4> { static constexpr int H = 16, W = 16, CI = 256, CO = 256; static constexpr bool POOL = true,  OUTF = false; };
template <> struct Cfg<5> { static constexpr int H = 8,  W = 8,  CI = 256, CO = 512; static constexpr bool POOL = false, OUTF = false; };
template <> struct Cfg<6> { static constexpr int H = 8,  W = 8,  CI = 512, CO = 512; static constexpr bool POOL = true,  OUTF = true;  };

template <int L> DEVFN const unsigned int* bc_in();
template <> DEVFN const unsigned int* bc_in<2>() { return g_xb1; }
template <> DEVFN const unsigned int* bc_in<3>() { return g_xb2; }
template <> DEVFN const unsigned int* bc_in<4>() { return g_xb3; }
template <> DEVFN const unsigned int* bc_in<5>() { return g_xb4; }
template <> DEVFN const unsigned int* bc_in<6>() { return g_xb5; }

template <int L> DEVFN unsigned int* bc_out();
template <> DEVFN unsigned int* bc_out<2>() { return g_xb2; }
template <> DEVFN unsigned int* bc_out<3>() { return g_xb3; }
template <> DEVFN unsigned int* bc_out<4>() { return g_xb4; }
template <> DEVFN unsigned int* bc_out<5>() { return g_xb5; }
template <> DEVFN unsigned int* bc_out<6>() { return g_xb5; }  // unused (OUTF)

template <int L> DEVFN unsigned int* wb_ptr();
template <> DEVFN unsigned int* wb_ptr<2>() { return g_wb2; }
template <> DEVFN unsigned int* wb_ptr<3>() { return g_wb3; }
template <> DEVFN unsigned int* wb_ptr<4>() { return g_wb4; }
template <> DEVFN unsigned int* wb_ptr<5>() { return g_wb5; }
template <> DEVFN unsigned int* wb_ptr<6>() { return g_wb6; }

// ---------------- fused weight sign-packing (all 5 layers, 1 launch) ---------
// Input HWIO: w[ky][kx][ci][co].  Output: wb[(tap*CO + co)*CIW + wi],
// bit b of word wi <-> ci = wi*32 + b, bit=1 <=> w > 0.
DEVFN void pack_one(const float* __restrict__ w, unsigned int* __restrict__ wb,
                    int CI, int CO, int idx) {
    int CIW = CI >> 5;
    int wi  = idx % CIW;
    int co  = (idx / CIW) % CO;
    int tap = idx / (CIW * CO);
    const float* src = w + (tap * CI + wi * 32) * CO + co;
    unsigned int word = 0;
    #pragma unroll 8
    for (int b = 0; b < 32; b++) {
        word |= (src[b * CO] > 0.f ? (1u << b) : 0u);
    }
    wb[idx] = word;
}

__global__ void __launch_bounds__(256) pack_all_kernel(
    const float* __restrict__ w2, const float* __restrict__ w3,
    const float* __restrict__ w4, const float* __restrict__ w5,
    const float* __restrict__ w6) {
    int t = blockIdx.x * 256 + threadIdx.x;
    // counts: L2 4608, L3 9216, L4 18432, L5 36864, L6 73728  (total 142848)
    if (t < 4608)        { pack_one(w2, g_wb2, 128, 128, t); return; }
    t -= 4608;
    if (t < 9216)        { pack_one(w3, g_wb3, 128, 256, t); return; }
    t -= 9216;
    if (t < 18432)       { pack_one(w4, g_wb4, 256, 256, t); return; }
    t -= 18432;
    if (t < 36864)       { pack_one(w5, g_wb5, 256, 512, t); return; }
    t -= 36864;
    if (t < 73728)       { pack_one(w6, g_wb6, 512, 512, t); return; }
}

// ---------------- conv1: fp32 conv + b1 + relu + bn1 -> sign bits -----------
// grid (32 rows, 128 images), block 128 (= output channels)
// Arithmetic mirrors XLA: conv = sequential FMA over (ky,kx,ci) from 0;
// then separately rounded +b1, relu, *scale, +bias.  (2-px ILP: two
// independent chains, per-output order identical to R5.)
__global__ void __launch_bounds__(128) conv1_kernel(
    const float* __restrict__ x,  const float* __restrict__ w1,
    const float* __restrict__ b1, const float* __restrict__ bn_s,
    const float* __restrict__ bn_b) {
    __shared__ float ws[27 * 128];
    __shared__ float xr[3][34][3];   // 3 rows, 34 cols (zero-padded), 3 ch
    int co = threadIdx.x;
    int y = blockIdx.x, n = blockIdx.y;

    for (int i = co; i < 27 * 128; i += 128) ws[i] = w1[i];
    for (int i = co; i < 3 * 34 * 3; i += 128) {
        int r = i / 102, rem = i % 102;
        int col = rem / 3, ci = rem % 3;
        int iy = y - 1 + r, ix = col - 1;
        float v = 0.f;
        if (iy >= 0 && iy < 32 && ix >= 0 && ix < 32)
            v = x[((n * 32 + iy) * 32 + ix) * 3 + ci];
        xr[r][col][ci] = v;
    }
    float sc = bn_s[co], bb = bn_b[co], bias1 = b1[co];
    __syncthreads();

    int lane = co & 31, wq = co >> 5;
    for (int xx = 0; xx < 32; xx += 2) {
        float acc0 = 0.f, acc1 = 0.f;
        #pragma unroll
        for (int ky = 0; ky < 3; ky++)
            #pragma unroll
            for (int kx = 0; kx < 3; kx++)
                #pragma unroll
                for (int ci = 0; ci < 3; ci++) {
                    float wv = ws[((ky * 3 + kx) * 3 + ci) * 128 + co];
                    acc0 = __fmaf_rn(xr[ky][xx + kx][ci],     wv, acc0);
                    acc1 = __fmaf_rn(xr[ky][xx + 1 + kx][ci], wv, acc1);
                }
        float h0 = fmaxf(__fadd_rn(acc0, bias1), 0.f);
        float f0 = __fadd_rn(__fmul_rn(h0, sc), bb);
        float h1 = fmaxf(__fadd_rn(acc1, bias1), 0.f);
        float f1 = __fadd_rn(__fmul_rn(h1, sc), bb);
        unsigned int bits0 = __ballot_sync(0xffffffffu, f0 > 0.f);
        unsigned int bits1 = __ballot_sync(0xffffffffu, f1 > 0.f);
        if (lane == 0) {
            g_xb1[((n * 32 + y) * 32 + xx) * 4 + wq]     = bits0;
            g_xb1[((n * 32 + y) * 32 + xx + 1) * 4 + wq] = bits1;
        }
    }
}

// ---------------- binary conv (fused relu/pool/bn/sign) ----------------------
// grid (N=128, CO/32), block 256. Warp lanes <-> 32 consecutive out-channels.
// ws layout: [tap][vec][lane] uint4 -> consecutive 16B per lane, LDS.128
// conflict-free. xs reads are warp-broadcast (same address, free).
template <int L>
__global__ void __launch_bounds__(256) binconv_kernel(
    const float* __restrict__ scale, const float* __restrict__ bias) {
    constexpr int  H = Cfg<L>::H, W = Cfg<L>::W, CI = Cfg<L>::CI, CO = Cfg<L>::CO;
    constexpr int  CIW  = CI / 32;
    constexpr int  CIWV = CIW / 4;
    constexpr bool POOL = Cfg<L>::POOL, OUTF = Cfg<L>::OUTF;

    __shared__ __align__(16) unsigned int xs[H * W * CIW];
    __shared__ __align__(16) uint4        wsv[9 * CIWV * 32];  // [tap][v][lane]

    int n = blockIdx.x, cg = blockIdx.y;
    int tid = threadIdx.x;

    const unsigned int* xin = bc_in<L>() + n * H * W * CIW;
    const unsigned int* wbg = wb_ptr<L>();
    for (int i = tid; i < H * W * CIW; i += 256) xs[i] = xin[i];
    {
        unsigned int* wsu = reinterpret_cast<unsigned int*>(wsv);
        for (int i = tid; i < 9 * 32 * CIW; i += 256) {
            int j   = i & 3;
            int ln  = (i >> 2) & 31;
            int vv  = (i >> 7) % CIWV;
            int tap = i / (32 * CIW);
            wsu[i] = wbg[(tap * CO + cg * 32 + ln) * CIW + vv * 4 + j];
        }
    }
    __syncthreads();

    int lane = tid & 31, warp = tid >> 5;
    int co = cg * 32 + lane;
    float sc = scale[co], bi = bias[co];

    if constexpr (POOL) {
        constexpr int PH = H / 2, PW = W / 2;
        for (int pp = warp; pp < PH * PW; pp += 8) {
            int py = pp / PW, px = pp % PW;
            int pops[4] = {0, 0, 0, 0};
            int taps[4] = {0, 0, 0, 0};
            #pragma unroll
            for (int ky = -1; ky <= 1; ky++)
                #pragma unroll
                for (int kx = -1; kx <= 1; kx++) {
                    int tap = (ky + 1) * 3 + kx + 1;
                    uint4 wr[CIWV];   // reused across the 4 pooled sub-pixels
                    #pragma unroll
                    for (int v = 0; v < CIWV; v++)
                        wr[v] = wsv[(tap * CIWV + v) * 32 + lane];
                    #pragma unroll
                    for (int s = 0; s < 4; s++) {
                        int y  = 2 * py + (s >> 1) + ky;
                        int xx = 2 * px + (s & 1) + kx;
                        if (y < 0 || y >= H || xx < 0 || xx >= W) continue;
                        taps[s]++;
                        const uint4* xp = reinterpret_cast<const uint4*>(&xs[(y * W + xx) * CIW]);
                        int p = 0;
                        #pragma unroll
                        for (int v = 0; v < CIWV; v++) {
                            uint4 a = xp[v];
                            p += __popc(a.x ^ wr[v].x) + __popc(a.y ^ wr[v].y)
                               + __popc(a.z ^ wr[v].z) + __popc(a.w ^ wr[v].w);
                        }
                        pops[s] += p;
                    }
                }
            int m = 0;  // relu(dot) then max-pool == max(0, max dots)
            #pragma unroll
            for (int s = 0; s < 4; s++) m = max(m, taps[s] * CI - 2 * pops[s]);
            float f = __fadd_rn(__fmul_rn((float)m, sc), bi);
            if constexpr (OUTF) {
                g_h6[((n * PH + py) * PW + px) * CO + co] = f;
            } else {
                unsigned int bits = __ballot_sync(0xffffffffu, f > 0.f);
                if (lane == 0)
                    bc_out<L>()[((n * PH + py) * PW + px) * (CO / 32) + cg] = bits;
            }
        }
    } else {
        // all 9 taps' weights resident in registers (9*CIWV uint4)
        uint4 wrAll[9][CIWV];
        #pragma unroll
        for (int t = 0; t < 9; t++)
            #pragma unroll
            for (int v = 0; v < CIWV; v++)
                wrAll[t][v] = wsv[(t * CIWV + v) * 32 + lane];

        for (int pp = warp; pp < H * W; pp += 8) {
            int y0 = pp / W, x0 = pp % W;
            int pop = 0, tapc = 0;
            #pragma unroll
            for (int ky = -1; ky <= 1; ky++)
                #pragma unroll
                for (int kx = -1; kx <= 1; kx++) {
                    int y = y0 + ky, xx = x0 + kx;
                    if (y < 0 || y >= H || xx < 0 || xx >= W) continue;
                    tapc++;
                    int tap = (ky + 1) * 3 + kx + 1;
                    const uint4* xp = reinterpret_cast<const uint4*>(&xs[(y * W + xx) * CIW]);
                    #pragma unroll
                    for (int v = 0; v < CIWV; v++) {
                        uint4 a = xp[v], b = wrAll[tap][v];
                        pop += __popc(a.x ^ b.x) + __popc(a.y ^ b.y)
                             + __popc(a.z ^ b.z) + __popc(a.w ^ b.w);
                    }
                }
            int dot = tapc * CI - 2 * pop;
            float f = __fadd_rn(__fmul_rn((float)max(dot, 0), sc), bi);  // relu then bn
            unsigned int bits = __ballot_sync(0xffffffffu, f > 0.f);
            if (lane == 0)
                bc_out<L>()[((n * H + y0) * W + x0) * (CO / 32) + cg] = bits;
        }
    }
}

// ---------------- fp32 dense(512->10) + softmax over last axis --------------
// one warp per (n, py, px): 128*16 = 2048 warps
__global__ void __launch_bounds__(256) dense_softmax_kernel(
    const float* __restrict__ dw, const float* __restrict__ db,
    float* __restrict__ out) {
    int gw = (blockIdx.x * blockDim.x + threadIdx.x) >> 5;
    int lane = threadIdx.x & 31;
    if (gw >= 2048) return;
    const float* hp = g_h6 + gw * 512;
    float acc[10];
    #pragma unroll
    for (int d = 0; d < 10; d++) acc[d] = 0.f;
    #pragma unroll 4
    for (int c = lane; c < 512; c += 32) {
        float hv = hp[c];
        #pragma unroll
        for (int d = 0; d < 10; d++)
            acc[d] = __fmaf_rn(hv, dw[c * 10 + d], acc[d]);
    }
    #pragma unroll
    for (int d = 0; d < 10; d++) {
        #pragma unroll
        for (int off = 16; off; off >>= 1)
            acc[d] += __shfl_xor_sync(0xffffffffu, acc[d], off);
    }
    if (lane == 0) {
        float mx = -1e30f;
        #pragma unroll
        for (int d = 0; d < 10; d++) {
            acc[d] = __fadd_rn(acc[d], db[d]);
            mx = fmaxf(mx, acc[d]);
        }
        float sum = 0.f;
        #pragma unroll
        for (int d = 0; d < 10; d++) {
            acc[d] = expf(__fadd_rn(acc[d], -mx));
            sum = __fadd_rn(sum, acc[d]);
        }
        #pragma unroll
        for (int d = 0; d < 10; d++) out[gw * 10 + d] = __fdiv_rn(acc[d], sum);
    }
}

// ---------------- launch ------------------------------------------------------
extern "C" void kernel_launch(void* const* d_in, const int* in_sizes, int n_in,
                              void* d_out, int out_size) {
    (void)n_in; (void)out_size;
    const float* x  = (const float*)d_in[0];
    const float* w1 = (const float*)d_in[1];
    const float* b1 = (const float*)d_in[2];

    // Resolve input ordering: dict order (w2 at idx 3, size 147456) vs
    // reference-signature order (bn1_scale at idx 3, size 128).
    int iw[7], ibs[7], ibb[7];
    if (in_sizes[3] == 147456) {           // dict order
        iw[2] = 3; iw[3] = 4; iw[4] = 5; iw[5] = 6; iw[6] = 7;
        for (int k = 1; k <= 6; k++) { ibs[k] = 8 + 2 * (k - 1); ibb[k] = 9 + 2 * (k - 1); }
    } else {                               // signature order
        ibs[1] = 3; ibb[1] = 4;
        for (int k = 2; k <= 6; k++) {
            iw[k]  = 5 + 3 * (k - 2);
            ibs[k] = 6 + 3 * (k - 2);
            ibb[k] = 7 + 3 * (k - 2);
        }
    }
    const float* dw = (const float*)d_in[20];
    const float* db = (const float*)d_in[21];
    float* out = (float*)d_out;

    // pack all binary weights in a single launch (142848 words)
    pack_all_kernel<<<(142848 + 255) / 256, 256>>>(
        (const float*)d_in[iw[2]], (const float*)d_in[iw[3]],
        (const float*)d_in[iw[4]], (const float*)d_in[iw[5]],
        (const float*)d_in[iw[6]]);

    conv1_kernel<<<dim3(32, 128), 128>>>(x, w1, b1,
        (const float*)d_in[ibs[1]], (const float*)d_in[ibb[1]]);

    binconv_kernel<2><<<dim3(128, 4),  256>>>((const float*)d_in[ibs[2]], (const float*)d_in[ibb[2]]);
    binconv_kernel<3><<<dim3(128, 8),  256>>>((const float*)d_in[ibs[3]], (const float*)d_in[ibb[3]]);
    binconv_kernel<4><<<dim3(128, 8),  256>>>((const float*)d_in[ibs[4]], (const float*)d_in[ibb[4]]);
    binconv_kernel<5><<<dim3(128, 16), 256>>>((const float*)d_in[ibs[5]], (const float*)d_in[ibb[5]]);
    binconv_kernel<6><<<dim3(128, 16), 256>>>((const float*)d_in[ibs[6]], (const float*)d_in[ibb[6]]);

    dense_softmax_kernel<<<256, 256>>>(dw, db, out);
}